// round 16
// baseline (speedup 1.0000x reference)
#include <cuda_runtime.h>
#include <cuda_bf16.h>
#include <cuda_fp16.h>
#include <math.h>

#define BB 2
#define C 256
#define NN 16384          // D*W*H = 16*32*32
#define SN 256
#define CS 256
#define HEADS 8
#define DH 32
#define EPSV 1e-6f

// ---------------- scratch (device globals; no allocations allowed) ----------
__device__ __nv_bfloat16 g_hnh[BB*C*NN];   // normalized x, bf16 [b][c][n]
__device__ __nv_bfloat16 g_qh [BB*C*NN];   // q projection,  bf16 [b][c][n]
__device__ __nv_bfloat16 g_aoh[BB*C*NN];   // attention out, bf16 [b][c][n]
__device__ __nv_bfloat16 g_kh [BB*C*SN];   // k bf16 [b][c][s]
__device__ __half        g_vh [BB*C*SN];   // v fp16 [b][c][s]  (PV mma is f16)
__device__ __nv_bfloat16 g_snh[BB*C*SN];   // LN(style) transposed, bf16 [b][c][n]
__device__ __nv_bfloat16 g_wqh[C*C];       // Wq bf16
__device__ __nv_bfloat16 g_woh[C*C];       // Wo bf16
__device__ __nv_bfloat16 g_wkvh[2*C*C];    // [Wk; Wv] stacked bf16 (512 x 256)

// ---------------- mma helpers ----------------------------------------------
__device__ __forceinline__ unsigned pack_bf16(float a, float b) {
    __nv_bfloat162 t = __floats2bfloat162_rn(a, b);   // a -> low, b -> high
    return *(unsigned*)&t;
}
__device__ __forceinline__ unsigned pack_f16(float a, float b) {
    __half2 t = __floats2half2_rn(a, b);              // a -> low, b -> high
    return *(unsigned*)&t;
}
__device__ __forceinline__ unsigned sptr(const void* p) {
    return (unsigned)__cvta_generic_to_shared(p);
}
__device__ __forceinline__ float ex2f(float x) {
    float y;
    asm("ex2.approx.f32 %0, %1;" : "=f"(y) : "f"(x));
    return y;
}
// pack two floats to half2 and exp2 both lanes in ONE MUFU op
__device__ __forceinline__ unsigned ex2h2(float a, float b) {
    __half2 h = __floats2half2_rn(a, b);
    unsigned u = *(unsigned*)&h, r;
    asm("ex2.approx.f16x2 %0, %1;" : "=r"(r) : "r"(u));
    return r;
}
__device__ __forceinline__ void mma16816(float* c, const unsigned* a, const unsigned* b) {
    asm volatile(
        "mma.sync.aligned.m16n8k16.row.col.f32.bf16.bf16.f32 "
        "{%0,%1,%2,%3}, {%4,%5,%6,%7}, {%8,%9}, {%0,%1,%2,%3};"
        : "+f"(c[0]), "+f"(c[1]), "+f"(c[2]), "+f"(c[3])
        : "r"(a[0]), "r"(a[1]), "r"(a[2]), "r"(a[3]), "r"(b[0]), "r"(b[1]));
}
__device__ __forceinline__ void mma16816f16(float* c, const unsigned* a, const unsigned* b) {
    asm volatile(
        "mma.sync.aligned.m16n8k16.row.col.f32.f16.f16.f32 "
        "{%0,%1,%2,%3}, {%4,%5,%6,%7}, {%8,%9}, {%0,%1,%2,%3};"
        : "+f"(c[0]), "+f"(c[1]), "+f"(c[2]), "+f"(c[3])
        : "r"(a[0]), "r"(a[1]), "r"(a[2]), "r"(a[3]), "r"(b[0]), "r"(b[1]));
}
__device__ __forceinline__ void ldsm_x4(unsigned* r, unsigned addr) {
    asm volatile("ldmatrix.sync.aligned.m8n8.x4.shared.b16 {%0,%1,%2,%3}, [%4];"
                 : "=r"(r[0]), "=r"(r[1]), "=r"(r[2]), "=r"(r[3]) : "r"(addr));
}
__device__ __forceinline__ void ldsm_x2_trans(unsigned* r, unsigned addr) {
    asm volatile("ldmatrix.sync.aligned.m8n8.x2.trans.shared.b16 {%0,%1}, [%2];"
                 : "=r"(r[0]), "=r"(r[1]) : "r"(addr));
}
__device__ __forceinline__ void cp16(unsigned smem_addr, const void* gptr) {
    asm volatile("cp.async.ca.shared.global [%0], [%1], 16;\n"
                 :: "r"(smem_addr), "l"(gptr));
}
__device__ __forceinline__ void cp_commit() {
    asm volatile("cp.async.commit_group;\n" ::);
}
template<int N> __device__ __forceinline__ void cp_wait() {
    asm volatile("cp.async.wait_group %0;\n" :: "n"(N));
}

// ---------------------------------------------------------------------------
// Kernel 1: fused prep = wconv (weights->bf16)  U  lns (style LN -> snT)
//                      U  lnx (channel LN of x -> bf16). Dispatch on blockIdx.
// grid: [0,1024) lnx | [1024,1536) lns | [1536,1664) wconv. 256 threads.
// ---------------------------------------------------------------------------
__global__ void __launch_bounds__(256) prep_kernel(
    const float* __restrict__ x,
    const float* __restrict__ ln_w,  const float* __restrict__ ln_b,
    const float* __restrict__ s,
    const float* __restrict__ lns_w, const float* __restrict__ lns_b,
    const float* __restrict__ Wq, const float* __restrict__ Wo,
    const float* __restrict__ Wk, const float* __restrict__ Wv)
{
    __shared__ float4 red[8][8][2];   // lnx reduction
    __shared__ float ws1[8], ws2[8], mu_s, rstd_s;   // lns reduction

    int bid = blockIdx.x;
    int tid = threadIdx.x;

    if (bid < 1024) {
        // ----- lnx: single pass, coalesced -----
        int b = bid >> 9;
        int blk = bid & 511;
        int lane = tid & 31, w = tid >> 5;
        int grp = tid & 7;
        int chunk = tid >> 3;
        int pos = blk*32 + grp*4;
        const float* xb = x + (size_t)b*C*NN + (size_t)chunk*8*NN + pos;

        float4 xv[8];
        float4 a1 = make_float4(0,0,0,0), a2 = make_float4(0,0,0,0);
        #pragma unroll
        for (int i = 0; i < 8; i++) {
            xv[i] = *(const float4*)(xb + (size_t)i*NN);
            a1.x += xv[i].x; a1.y += xv[i].y; a1.z += xv[i].z; a1.w += xv[i].w;
            a2.x += xv[i].x*xv[i].x; a2.y += xv[i].y*xv[i].y;
            a2.z += xv[i].z*xv[i].z; a2.w += xv[i].w*xv[i].w;
        }
        #pragma unroll
        for (int m = 8; m <= 16; m <<= 1) {
            a1.x += __shfl_xor_sync(0xffffffffu, a1.x, m);
            a1.y += __shfl_xor_sync(0xffffffffu, a1.y, m);
            a1.z += __shfl_xor_sync(0xffffffffu, a1.z, m);
            a1.w += __shfl_xor_sync(0xffffffffu, a1.w, m);
            a2.x += __shfl_xor_sync(0xffffffffu, a2.x, m);
            a2.y += __shfl_xor_sync(0xffffffffu, a2.y, m);
            a2.z += __shfl_xor_sync(0xffffffffu, a2.z, m);
            a2.w += __shfl_xor_sync(0xffffffffu, a2.w, m);
        }
        if (lane < 8) { red[w][lane][0] = a1; red[w][lane][1] = a2; }
        __syncthreads();

        float4 s1 = make_float4(0,0,0,0), s2 = make_float4(0,0,0,0);
        #pragma unroll
        for (int ww = 0; ww < 8; ww++) {
            float4 p1 = red[ww][grp][0], p2 = red[ww][grp][1];
            s1.x += p1.x; s1.y += p1.y; s1.z += p1.z; s1.w += p1.w;
            s2.x += p2.x; s2.y += p2.y; s2.z += p2.z; s2.w += p2.w;
        }
        float4 mean, rstd;
        mean.x = s1.x*(1.f/C); mean.y = s1.y*(1.f/C);
        mean.z = s1.z*(1.f/C); mean.w = s1.w*(1.f/C);
        rstd.x = rsqrtf(s2.x*(1.f/C) - mean.x*mean.x + EPSV);
        rstd.y = rsqrtf(s2.y*(1.f/C) - mean.y*mean.y + EPSV);
        rstd.z = rsqrtf(s2.z*(1.f/C) - mean.z*mean.z + EPSV);
        rstd.w = rsqrtf(s2.w*(1.f/C) - mean.w*mean.w + EPSV);

        __nv_bfloat16* hb = g_hnh + (size_t)b*C*NN + (size_t)chunk*8*NN + pos;
        const float4* wv4 = (const float4*)(ln_w + chunk*8);
        const float4* bv4 = (const float4*)(ln_b + chunk*8);
        #pragma unroll
        for (int i4 = 0; i4 < 2; i4++) {
            float4 wc = wv4[i4], bc = bv4[i4];
            float wcs[4] = {wc.x, wc.y, wc.z, wc.w};
            float bcs[4] = {bc.x, bc.y, bc.z, bc.w};
            #pragma unroll
            for (int j = 0; j < 4; j++) {
                int i = i4*4 + j;
                float o0 = (xv[i].x - mean.x)*rstd.x*wcs[j] + bcs[j];
                float o1 = (xv[i].y - mean.y)*rstd.y*wcs[j] + bcs[j];
                float o2 = (xv[i].z - mean.z)*rstd.z*wcs[j] + bcs[j];
                float o3 = (xv[i].w - mean.w)*rstd.w*wcs[j] + bcs[j];
                uint2 pk;
                pk.x = pack_bf16(o0, o1);
                pk.y = pack_bf16(o2, o3);
                *(uint2*)(hb + (size_t)i*NN) = pk;
            }
        }
    } else if (bid < 1536) {
        // ----- lns: style LN -> snT bf16 -----
        int t2 = bid - 1024;
        int b = t2 / SN, n = t2 % SN;
        int t = tid;
        const float* srow = s + ((size_t)b*SN + n)*CS;
        float val = srow[t];
        float s1 = val, s2 = val*val;
        #pragma unroll
        for (int o = 16; o > 0; o >>= 1) {
            s1 += __shfl_xor_sync(0xffffffffu, s1, o);
            s2 += __shfl_xor_sync(0xffffffffu, s2, o);
        }
        int lane = t & 31, wid = t >> 5;
        if (lane == 0) { ws1[wid] = s1; ws2[wid] = s2; }
        __syncthreads();
        if (t == 0) {
            float a = 0.f, b2 = 0.f;
            #pragma unroll
            for (int i = 0; i < 8; i++) { a += ws1[i]; b2 += ws2[i]; }
            float mu = a / CS;
            float var = b2 / CS - mu*mu;
            mu_s = mu;
            rstd_s = rsqrtf(var + EPSV);
        }
        __syncthreads();
        float v = (val - mu_s) * rstd_s * lns_w[t] + lns_b[t];
        g_snh[((size_t)b*C + t)*SN + n] = __float2bfloat16(v);
    } else {
        // ----- wconv: weights -> bf16 -----
        int i = (bid - 1536) * 256 + tid;   // over C*C/2 pairs
        float2 a = ((const float2*)Wq)[i];
        ((unsigned*)g_wqh)[i] = pack_bf16(a.x, a.y);
        float2 b = ((const float2*)Wo)[i];
        ((unsigned*)g_woh)[i] = pack_bf16(b.x, b.y);
        float2 c = ((const float2*)Wk)[i];
        ((unsigned*)g_wkvh)[i] = pack_bf16(c.x, c.y);
        float2 d = ((const float2*)Wv)[i];
        ((unsigned*)g_wkvh)[i + C*C/2] = pack_bf16(d.x, d.y);
    }
}

// ---------------------------------------------------------------------------
// Shared GEMM mainloop (2-stage, BK=32), CTA tile 128(m) x 64(n), 8 warps
// in a 4(m) x 2(n) grid, warp tile 32x32. ~80 regs -> 3 CTAs/SM.
// acc[b,o,n] += sum_c W[o,c] * In[b,c,n] over c=0..255.
// ---------------------------------------------------------------------------
__device__ __forceinline__ void gemm_mainloop(
    const __nv_bfloat16* __restrict__ Wh,
    const __nv_bfloat16* __restrict__ Inb,
    int nb, int om, int nsize, int tid,
    float (&acc)[2][4][4],
    __nv_bfloat16 (&As)[2][128][40],
    __nv_bfloat16 (&Bs)[2][32][72])
{
    int w = tid >> 5, lane = tid & 31;
    int wr = w >> 1, wc = w & 1;       // warp grid 4(m) x 2(n)

    int arow = tid >> 1, acol = (tid & 1) * 16;
    int brow = tid >> 3, bseg = (tid & 7) * 8;

    auto stage = [&](int buf, int k0) {
        const __nv_bfloat16* ap = Wh + (size_t)(om + arow)*C + k0 + acol;
        cp16(sptr(&As[buf][arow][acol]),     ap);
        cp16(sptr(&As[buf][arow][acol + 8]), ap + 8);
        cp16(sptr(&Bs[buf][brow][bseg]),
             Inb + (size_t)(k0 + brow)*nsize + nb + bseg);
        cp_commit();
    };

    #pragma unroll
    for (int mi = 0; mi < 2; mi++)
        #pragma unroll
        for (int nj = 0; nj < 4; nj++)
            #pragma unroll
            for (int q = 0; q < 4; q++) acc[mi][nj][q] = 0.f;

    stage(0, 0);

    #pragma unroll 1
    for (int ks = 0; ks < 8; ks++) {
        int buf = ks & 1;
        cp_wait<0>();
        __syncthreads();

        // k half 0 (cols 0..15)
        unsigned afr[2][4], bfr[4][2];
        #pragma unroll
        for (int mi = 0; mi < 2; mi++)
            ldsm_x4(afr[mi], sptr(&As[buf][32*wr + 16*mi + (lane & 15)][(lane >> 4) * 8]));
        #pragma unroll
        for (int nj = 0; nj < 4; nj++)
            ldsm_x2_trans(bfr[nj], sptr(&Bs[buf][lane & 15][32*wc + 8*nj]));

        if (ks < 7) stage(buf ^ 1, (ks + 1) * 32);

        #pragma unroll
        for (int nj = 0; nj < 4; nj++)
            #pragma unroll
            for (int mi = 0; mi < 2; mi++)
                mma16816(acc[mi][nj], afr[mi], bfr[nj]);

        // k half 1 (cols 16..31)
        #pragma unroll
        for (int mi = 0; mi < 2; mi++)
            ldsm_x4(afr[mi], sptr(&As[buf][32*wr + 16*mi + (lane & 15)][16 + (lane >> 4) * 8]));
        #pragma unroll
        for (int nj = 0; nj < 4; nj++)
            ldsm_x2_trans(bfr[nj], sptr(&Bs[buf][16 + (lane & 15)][32*wc + 8*nj]));
        #pragma unroll
        for (int nj = 0; nj < 4; nj++)
            #pragma unroll
            for (int mi = 0; mi < 2; mi++)
                mma16816(acc[mi][nj], afr[mi], bfr[nj]);
    }
}

// ---------------------------------------------------------------------------
// Kernel 2: fused Q-GEMM + KV-GEMM. grid (256, 3, BB):
// y<2 -> Q (om=y*128, nb=x*64, bf16 out);
// y==2 -> KV (x<16): om=(x>>2)*128, nb=(x&3)*64; K rows -> bf16, V -> fp16.
// ---------------------------------------------------------------------------
__global__ void __launch_bounds__(256) qkv_gemm() {
    __shared__ __nv_bfloat16 As[2][128][40];
    __shared__ __nv_bfloat16 Bs[2][32][72];

    int tid = threadIdx.x, w = tid >> 5, lane = tid & 31;
    int wr = w >> 1, wc = w & 1;
    int g = lane >> 2, tig = lane & 3;
    int b = blockIdx.z;
    float acc[2][4][4];

    if (blockIdx.y < 2) {
        int nb = blockIdx.x * 64, om = blockIdx.y * 128;
        gemm_mainloop(g_wqh, g_hnh + (size_t)b*C*NN, nb, om, NN, tid, acc, As, Bs);
        #pragma unroll
        for (int mi = 0; mi < 2; mi++) {
            int o = om + 32*wr + 16*mi + g;
            #pragma unroll
            for (int nj = 0; nj < 4; nj++) {
                int n = nb + 32*wc + 8*nj + 2*tig;
                size_t base0 = ((size_t)b*C + o)*NN + n;
                size_t base1 = ((size_t)b*C + o + 8)*NN + n;
                *(unsigned*)(g_qh + base0) = pack_bf16(acc[mi][nj][0], acc[mi][nj][1]);
                *(unsigned*)(g_qh + base1) = pack_bf16(acc[mi][nj][2], acc[mi][nj][3]);
            }
        }
    } else {
        if (blockIdx.x >= 16) return;
        int nb = (blockIdx.x & 3) * 64, om = (blockIdx.x >> 2) * 128;
        gemm_mainloop(g_wkvh, g_snh + (size_t)b*C*SN, nb, om, SN, tid, acc, As, Bs);
        #pragma unroll
        for (int mi = 0; mi < 2; mi++) {
            int o = om + 32*wr + 16*mi + g;
            #pragma unroll
            for (int nj = 0; nj < 4; nj++) {
                int n = nb + 32*wc + 8*nj + 2*tig;
                int oo = o & 255;
                size_t base0 = ((size_t)b*C + oo)*SN + n;
                size_t base1 = ((size_t)b*C + oo + 8)*SN + n;
                if (o < 256) {   // K -> bf16
                    *(unsigned*)(g_kh + base0) = pack_bf16(acc[mi][nj][0], acc[mi][nj][1]);
                    *(unsigned*)(g_kh + base1) = pack_bf16(acc[mi][nj][2], acc[mi][nj][3]);
                } else {         // V -> fp16
                    *(unsigned*)(g_vh + base0) = pack_f16(acc[mi][nj][0], acc[mi][nj][1]);
                    *(unsigned*)(g_vh + base1) = pack_f16(acc[mi][nj][2], acc[mi][nj][3]);
                }
            }
        }
    }
}

// ---------------------------------------------------------------------------
// Kernel 4: O-GEMM, fp32 out + bias + residual. grid (NN/64, C/128, BB).
// ---------------------------------------------------------------------------
__global__ void __launch_bounds__(256) o_gemm(float* __restrict__ OutF,
                                              const float* __restrict__ bias,
                                              const float* __restrict__ resid) {
    __shared__ __nv_bfloat16 As[2][128][40];
    __shared__ __nv_bfloat16 Bs[2][32][72];

    int tid = threadIdx.x, w = tid >> 5, lane = tid & 31;
    int wr = w >> 1, wc = w & 1;
    int g = lane >> 2, tig = lane & 3;
    int b = blockIdx.z;
    int nb = blockIdx.x * 64, om = blockIdx.y * 128;
    float acc[2][4][4];

    gemm_mainloop(g_woh, g_aoh + (size_t)b*C*NN, nb, om, NN, tid, acc, As, Bs);

    #pragma unroll
    for (int mi = 0; mi < 2; mi++) {
        int o = om + 32*wr + 16*mi + g;
        #pragma unroll
        for (int nj = 0; nj < 4; nj++) {
            int n = nb + 32*wc + 8*nj + 2*tig;
            size_t base0 = ((size_t)b*C + o)*NN + n;
            size_t base1 = ((size_t)b*C + o + 8)*NN + n;
            float bo0 = bias[o], bo1 = bias[o+8];
            float2 x0 = *(const float2*)(resid + base0);
            float2 x1 = *(const float2*)(resid + base1);
            float2 r0, r1;
            r0.x = acc[mi][nj][0] + bo0 + x0.x;
            r0.y = acc[mi][nj][1] + bo0 + x0.y;
            r1.x = acc[mi][nj][2] + bo1 + x1.x;
            r1.y = acc[mi][nj][3] + bo1 + x1.y;
            *(float2*)(OutF + base0) = r0;
            *(float2*)(OutF + base1) = r1;
        }
    }
}

// ---------------------------------------------------------------------------
// Kernel 3: attention. S = QK^T in bf16 mma; softmax exp via ex2.approx.f16x2
// (outputs ARE the fp16 PV A-fragments); l via extra mma against constant
// all-ones fp16 B-fragment. grid (NN/128, HEADS, BB), 256 threads (8 warps).
// ---------------------------------------------------------------------------
__global__ void __launch_bounds__(256) attn_kernel() {
    __shared__ __nv_bfloat16 qsh[128][34];   // Q [pos][d]; reused as O staging
    __shared__ __nv_bfloat16 ksh[SN][40];    // K [s][d]
    __shared__ __half        vsh[DH][264];   // V [d][s]  fp16

    int b = blockIdx.z, h = blockIdx.y;
    int nb = blockIdx.x * 128;
    int tid = threadIdx.x, w = tid >> 5, lane = tid & 31;
    int g = lane >> 2, tig = lane & 3;

    const __nv_bfloat16* kb = g_kh + ((size_t)b*C + h*DH)*SN;
    const __half*        vb = g_vh + ((size_t)b*C + h*DH)*SN;
    const __nv_bfloat16* qb = g_qh + ((size_t)b*C + h*DH)*NN;

    #pragma unroll
    for (int i = tid; i < DH*SN/8; i += 256) {
        int d = i & 31, cs = i >> 5;
        __nv_bfloat16 tmp[8];
        *(uint4*)tmp = *(const uint4*)(kb + (size_t)d*SN + cs*8);
        #pragma unroll
        for (int j = 0; j < 8; j++) ksh[cs*8 + j][d] = tmp[j];
    }
    #pragma unroll
    for (int i = tid; i < DH*SN/8; i += 256) {
        int d = i >> 5, cs = i & 31;
        *(uint4*)&vsh[d][cs*8] = *(const uint4*)(vb + (size_t)d*SN + cs*8);
    }
    {
        // fold softmax scale AND log2(e) into Q (softmax runs in exp2 domain)
        const float scf = 0.17677669529663689f * 1.4426950408889634f;
        const __nv_bfloat162 sc2 = __floats2bfloat162_rn(scf, scf);
        #pragma unroll
        for (int i = tid; i < 128*DH/8; i += 256) {
            int d = i >> 4, pc = i & 15;
            __nv_bfloat162 tmp[4];
            *(uint4*)tmp = *(const uint4*)(qb + (size_t)d*NN + nb + pc*8);
            #pragma unroll
            for (int j = 0; j < 4; j++) {
                __nv_bfloat162 v = __hmul2(tmp[j], sc2);
                qsh[pc*8 + 2*j    ][d] = __low2bfloat16(v);
                qsh[pc*8 + 2*j + 1][d] = __high2bfloat16(v);
            }
        }
    }
    __syncthreads();

    unsigned aq[2][4];
    {
        int m0 = 16*w;
        #pragma unroll
        for (int kg = 0; kg < 2; kg++) {
            int kc = 16*kg + 2*tig;
            aq[kg][0] = *(const unsigned*)&qsh[m0+g  ][kc];
            aq[kg][1] = *(const unsigned*)&qsh[m0+g+8][kc];
            aq[kg][2] = *(const unsigned*)&qsh[m0+g  ][kc+8];
            aq[kg][3] = *(const unsigned*)&qsh[m0+g+8][kc+8];
        }
    }

    float m0r = -INFINITY, m1r = -INFINITY;
    float oc[4][4];
    #pragma unroll
    for (int jj = 0; jj < 4; jj++)
        #pragma unroll
        for (int q = 0; q < 4; q++) oc[jj][q] = 0.f;
    float lacc[4] = {0.f, 0.f, 0.f, 0.f};   // l row-sums via ones-mma

    // precomputed ldmatrix address components
    int k_lrow = lane & 7, k_lcol = (lane >> 3) * 8;            // for ksh x4
    int v_mat = lane >> 3;
    int v_rlo = 8 * (v_mat >> 1) + (lane & 7);                  // row within 16-d group
    int v_col8 = 8 * (v_mat & 1);                               // s-half

    const unsigned bones[2] = {0x3C003C00u, 0x3C003C00u};       // fp16 1.0 x2

    for (int s0 = 0; s0 < SN; s0 += 64) {
        // --- S tile: 16 rows x 64 tokens; B-frags via ldmatrix.x4 ---
        float sc[8][4];
        #pragma unroll
        for (int j = 0; j < 8; j++) {
            sc[j][0] = sc[j][1] = sc[j][2] = sc[j][3] = 0.f;
            unsigned bk4[4];
            ldsm_x4(bk4, sptr(&ksh[s0 + 8*j + k_lrow][k_lcol]));
            mma16816(sc[j], aq[0], bk4);
            mma16816(sc[j], aq[1], bk4 + 2);
        }

        // --- online softmax: max, corr, f16x2 exp (results = A-fragments) ---
        float cm0 = -INFINITY, cm1 = -INFINITY;
        #pragma unroll
        for (int j = 0; j < 8; j++) {
            cm0 = fmaxf(cm0, fmaxf(sc[j][0], sc[j][1]));
            cm1 = fmaxf(cm1, fmaxf(sc[j][2], sc[j][3]));
        }
        cm0 = fmaxf(cm0, __shfl_xor_sync(0xffffffffu, cm0, 1));
        cm0 = fmaxf(cm0, __shfl_xor_sync(0xffffffffu, cm0, 2));
        cm1 = fmaxf(cm1, __shfl_xor_sync(0xffffffffu, cm1, 1));
        cm1 = fmaxf(cm1, __shfl_xor_sync(0xffffffffu, cm1, 2));

        float nm0 = fmaxf(m0r, cm0), nm1 = fmaxf(m1r, cm1);
        float corr0 = ex2f(m0r - nm0), corr1 = ex2f(m1r - nm1);
        m0r = nm0; m1r = nm1;

        unsigned ap[4][4];
        #pragma unroll
        for (int j = 0; j < 8; j++) {
            unsigned lo = ex2h2(sc[j][0] - nm0, sc[j][1] - nm0);
            unsigned hi = ex2h2(sc[j][2] - nm1, sc[j][3] - nm1);
            ap[j >> 1][(j & 1) * 2    ] = lo;
            ap[j >> 1][(j & 1) * 2 + 1] = hi;
        }

        #pragma unroll
        for (int jj = 0; jj < 4; jj++) {
            oc[jj][0] *= corr0; oc[jj][1] *= corr0;
            oc[jj][2] *= corr1; oc[jj][3] *= corr1;
        }
        lacc[0] *= corr0; lacc[1] *= corr0;
        lacc[2] *= corr1; lacc[3] *= corr1;

        // --- O += P V (f16 mma); l += P * ones ---
        #pragma unroll
        for (int kg = 0; kg < 4; kg++) {
            int scb = s0 + 16*kg + v_col8;
            #pragma unroll
            for (int p = 0; p < 2; p++) {
                unsigned bv4[4];
                ldsm_x4(bv4, sptr(&vsh[16*p + v_rlo][scb]));
                mma16816f16(oc[2*p],     ap[kg], bv4);
                mma16816f16(oc[2*p + 1], ap[kg], bv4 + 2);
            }
            mma16816f16(lacc, ap[kg], bones);
        }
    }

    float inv0 = 1.f / lacc[0], inv1 = 1.f / lacc[2];
    __syncthreads();
    #pragma unroll
    for (int jj = 0; jj < 4; jj++) {
        int col = 8*jj + 2*tig;
        *(unsigned*)&qsh[16*w+g  ][col] = pack_bf16(oc[jj][0]*inv0, oc[jj][1]*inv0);
        *(unsigned*)&qsh[16*w+g+8][col] = pack_bf16(oc[jj][2]*inv1, oc[jj][3]*inv1);
    }
    __syncthreads();
    #pragma unroll
    for (int i = tid; i < 128*DH/8; i += 256) {
        int d = i >> 4, pc = i & 15;
        __nv_bfloat16 tmp[8];
        #pragma unroll
        for (int j = 0; j < 8; j++) tmp[j] = qsh[pc*8 + j][d];
        *(uint4*)(g_aoh + ((size_t)b*C + h*DH + d)*NN + nb + pc*8) = *(uint4*)tmp;
    }
}

// ---------------------------------------------------------------------------
extern "C" void kernel_launch(void* const* d_in, const int* in_sizes, int n_in,
                              void* d_out, int out_size) {
    const float* x     = (const float*)d_in[0];
    const float* s     = (const float*)d_in[1];
    const float* ln_w  = (const float*)d_in[2];
    const float* ln_b  = (const float*)d_in[3];
    const float* lns_w = (const float*)d_in[4];
    const float* lns_b = (const float*)d_in[5];
    const float* Wq    = (const float*)d_in[6];
    const float* Wk    = (const float*)d_in[7];
    const float* Wv    = (const float*)d_in[8];
    const float* Wo    = (const float*)d_in[9];
    const float* bo    = (const float*)d_in[10];
    float* out = (float*)d_out;

    // 1: fused prep (wconv + lns + lnx)
    prep_kernel<<<1664, 256>>>(x, ln_w, ln_b, s, lns_w, lns_b, Wq, Wo, Wk, Wv);

    // 2: fused Q + KV GEMMs
    {
        dim3 grid(NN/64, 3, BB);
        qkv_gemm<<<grid, 256>>>();
    }

    // 3: attention
    {
        dim3 grid(NN/128, HEADS, BB);
        attn_kernel<<<grid, 256>>>();
    }

    // 4: out = Wo @ ao + bo + x
    {
        dim3 grid(NN/64, C/128, BB);
        o_gemm<<<grid, 256>>>(out, bo, x);
    }
}

// round 17
// speedup vs baseline: 1.0616x; 1.0616x over previous
#include <cuda_runtime.h>
#include <cuda_bf16.h>
#include <cuda_fp16.h>
#include <math.h>

#define BB 2
#define C 256
#define NN 16384          // D*W*H = 16*32*32
#define SN 256
#define CS 256
#define HEADS 8
#define DH 32
#define EPSV 1e-6f

// ---------------- scratch (device globals; no allocations allowed) ----------
__device__ __nv_bfloat16 g_hnh[BB*C*NN];   // normalized x, bf16 [b][c][n]
__device__ __nv_bfloat16 g_qh [BB*C*NN];   // q projection,  bf16 [b][c][n]
__device__ __nv_bfloat16 g_aoh[BB*C*NN];   // attention out, bf16 [b][c][n]
__device__ __nv_bfloat16 g_kh [BB*C*SN];   // k bf16 [b][c][s]
__device__ __half        g_vh [BB*C*SN];   // v fp16 [b][c][s]  (PV mma is f16)
__device__ __nv_bfloat16 g_snh[BB*C*SN];   // LN(style) transposed, bf16 [b][c][n]
__device__ __nv_bfloat16 g_wqh[C*C];       // Wq bf16
__device__ __nv_bfloat16 g_woh[C*C];       // Wo bf16
__device__ __nv_bfloat16 g_wkvh[2*C*C];    // [Wk; Wv] stacked bf16 (512 x 256)

// ---------------- mma helpers ----------------------------------------------
__device__ __forceinline__ unsigned pack_bf16(float a, float b) {
    __nv_bfloat162 t = __floats2bfloat162_rn(a, b);   // a -> low, b -> high
    return *(unsigned*)&t;
}
__device__ __forceinline__ unsigned pack_f16(float a, float b) {
    __half2 t = __floats2half2_rn(a, b);              // a -> low, b -> high
    return *(unsigned*)&t;
}
__device__ __forceinline__ unsigned sptr(const void* p) {
    return (unsigned)__cvta_generic_to_shared(p);
}
__device__ __forceinline__ float ex2f(float x) {
    float y;
    asm("ex2.approx.f32 %0, %1;" : "=f"(y) : "f"(x));
    return y;
}
// pack two floats to half2 and exp2 both lanes in ONE MUFU op
__device__ __forceinline__ unsigned ex2h2(float a, float b) {
    __half2 h = __floats2half2_rn(a, b);
    unsigned u = *(unsigned*)&h, r;
    asm("ex2.approx.f16x2 %0, %1;" : "=r"(r) : "r"(u));
    return r;
}
__device__ __forceinline__ void mma16816(float* c, const unsigned* a, const unsigned* b) {
    asm volatile(
        "mma.sync.aligned.m16n8k16.row.col.f32.bf16.bf16.f32 "
        "{%0,%1,%2,%3}, {%4,%5,%6,%7}, {%8,%9}, {%0,%1,%2,%3};"
        : "+f"(c[0]), "+f"(c[1]), "+f"(c[2]), "+f"(c[3])
        : "r"(a[0]), "r"(a[1]), "r"(a[2]), "r"(a[3]), "r"(b[0]), "r"(b[1]));
}
__device__ __forceinline__ void mma16816f16(float* c, const unsigned* a, const unsigned* b) {
    asm volatile(
        "mma.sync.aligned.m16n8k16.row.col.f32.f16.f16.f32 "
        "{%0,%1,%2,%3}, {%4,%5,%6,%7}, {%8,%9}, {%0,%1,%2,%3};"
        : "+f"(c[0]), "+f"(c[1]), "+f"(c[2]), "+f"(c[3])
        : "r"(a[0]), "r"(a[1]), "r"(a[2]), "r"(a[3]), "r"(b[0]), "r"(b[1]));
}
__device__ __forceinline__ void ldsm_x4(unsigned* r, unsigned addr) {
    asm volatile("ldmatrix.sync.aligned.m8n8.x4.shared.b16 {%0,%1,%2,%3}, [%4];"
                 : "=r"(r[0]), "=r"(r[1]), "=r"(r[2]), "=r"(r[3]) : "r"(addr));
}
__device__ __forceinline__ void ldsm_x4_trans(unsigned* r, unsigned addr) {
    asm volatile("ldmatrix.sync.aligned.m8n8.x4.trans.shared.b16 {%0,%1,%2,%3}, [%4];"
                 : "=r"(r[0]), "=r"(r[1]), "=r"(r[2]), "=r"(r[3]) : "r"(addr));
}
__device__ __forceinline__ void cp16(unsigned smem_addr, const void* gptr) {
    asm volatile("cp.async.ca.shared.global [%0], [%1], 16;\n"
                 :: "r"(smem_addr), "l"(gptr));
}
__device__ __forceinline__ void cp_commit() {
    asm volatile("cp.async.commit_group;\n" ::);
}
template<int N> __device__ __forceinline__ void cp_wait() {
    asm volatile("cp.async.wait_group %0;\n" :: "n"(N));
}

// ---------------------------------------------------------------------------
// Kernel 1: fused prep = wconv (weights->bf16)  U  lns (style LN -> snT)
//                      U  lnx (channel LN of x -> bf16). Dispatch on blockIdx.
// grid: [0,1024) lnx | [1024,1536) lns | [1536,1664) wconv. 256 threads.
// ---------------------------------------------------------------------------
__global__ void __launch_bounds__(256) prep_kernel(
    const float* __restrict__ x,
    const float* __restrict__ ln_w,  const float* __restrict__ ln_b,
    const float* __restrict__ s,
    const float* __restrict__ lns_w, const float* __restrict__ lns_b,
    const float* __restrict__ Wq, const float* __restrict__ Wo,
    const float* __restrict__ Wk, const float* __restrict__ Wv)
{
    __shared__ float4 red[8][8][2];   // lnx reduction
    __shared__ float ws1[8], ws2[8], mu_s, rstd_s;   // lns reduction

    int bid = blockIdx.x;
    int tid = threadIdx.x;

    if (bid < 1024) {
        // ----- lnx: single pass, coalesced -----
        int b = bid >> 9;
        int blk = bid & 511;
        int lane = tid & 31, w = tid >> 5;
        int grp = tid & 7;
        int chunk = tid >> 3;
        int pos = blk*32 + grp*4;
        const float* xb = x + (size_t)b*C*NN + (size_t)chunk*8*NN + pos;

        float4 xv[8];
        float4 a1 = make_float4(0,0,0,0), a2 = make_float4(0,0,0,0);
        #pragma unroll
        for (int i = 0; i < 8; i++) {
            xv[i] = *(const float4*)(xb + (size_t)i*NN);
            a1.x += xv[i].x; a1.y += xv[i].y; a1.z += xv[i].z; a1.w += xv[i].w;
            a2.x += xv[i].x*xv[i].x; a2.y += xv[i].y*xv[i].y;
            a2.z += xv[i].z*xv[i].z; a2.w += xv[i].w*xv[i].w;
        }
        #pragma unroll
        for (int m = 8; m <= 16; m <<= 1) {
            a1.x += __shfl_xor_sync(0xffffffffu, a1.x, m);
            a1.y += __shfl_xor_sync(0xffffffffu, a1.y, m);
            a1.z += __shfl_xor_sync(0xffffffffu, a1.z, m);
            a1.w += __shfl_xor_sync(0xffffffffu, a1.w, m);
            a2.x += __shfl_xor_sync(0xffffffffu, a2.x, m);
            a2.y += __shfl_xor_sync(0xffffffffu, a2.y, m);
            a2.z += __shfl_xor_sync(0xffffffffu, a2.z, m);
            a2.w += __shfl_xor_sync(0xffffffffu, a2.w, m);
        }
        if (lane < 8) { red[w][lane][0] = a1; red[w][lane][1] = a2; }
        __syncthreads();

        float4 s1 = make_float4(0,0,0,0), s2 = make_float4(0,0,0,0);
        #pragma unroll
        for (int ww = 0; ww < 8; ww++) {
            float4 p1 = red[ww][grp][0], p2 = red[ww][grp][1];
            s1.x += p1.x; s1.y += p1.y; s1.z += p1.z; s1.w += p1.w;
            s2.x += p2.x; s2.y += p2.y; s2.z += p2.z; s2.w += p2.w;
        }
        float4 mean, rstd;
        mean.x = s1.x*(1.f/C); mean.y = s1.y*(1.f/C);
        mean.z = s1.z*(1.f/C); mean.w = s1.w*(1.f/C);
        rstd.x = rsqrtf(s2.x*(1.f/C) - mean.x*mean.x + EPSV);
        rstd.y = rsqrtf(s2.y*(1.f/C) - mean.y*mean.y + EPSV);
        rstd.z = rsqrtf(s2.z*(1.f/C) - mean.z*mean.z + EPSV);
        rstd.w = rsqrtf(s2.w*(1.f/C) - mean.w*mean.w + EPSV);

        __nv_bfloat16* hb = g_hnh + (size_t)b*C*NN + (size_t)chunk*8*NN + pos;
        const float4* wv4 = (const float4*)(ln_w + chunk*8);
        const float4* bv4 = (const float4*)(ln_b + chunk*8);
        #pragma unroll
        for (int i4 = 0; i4 < 2; i4++) {
            float4 wc = wv4[i4], bc = bv4[i4];
            float wcs[4] = {wc.x, wc.y, wc.z, wc.w};
            float bcs[4] = {bc.x, bc.y, bc.z, bc.w};
            #pragma unroll
            for (int j = 0; j < 4; j++) {
                int i = i4*4 + j;
                float o0 = (xv[i].x - mean.x)*rstd.x*wcs[j] + bcs[j];
                float o1 = (xv[i].y - mean.y)*rstd.y*wcs[j] + bcs[j];
                float o2 = (xv[i].z - mean.z)*rstd.z*wcs[j] + bcs[j];
                float o3 = (xv[i].w - mean.w)*rstd.w*wcs[j] + bcs[j];
                uint2 pk;
                pk.x = pack_bf16(o0, o1);
                pk.y = pack_bf16(o2, o3);
                *(uint2*)(hb + (size_t)i*NN) = pk;
            }
        }
    } else if (bid < 1536) {
        // ----- lns: style LN -> snT bf16 -----
        int t2 = bid - 1024;
        int b = t2 / SN, n = t2 % SN;
        int t = tid;
        const float* srow = s + ((size_t)b*SN + n)*CS;
        float val = srow[t];
        float s1 = val, s2 = val*val;
        #pragma unroll
        for (int o = 16; o > 0; o >>= 1) {
            s1 += __shfl_xor_sync(0xffffffffu, s1, o);
            s2 += __shfl_xor_sync(0xffffffffu, s2, o);
        }
        int lane = t & 31, wid = t >> 5;
        if (lane == 0) { ws1[wid] = s1; ws2[wid] = s2; }
        __syncthreads();
        if (t == 0) {
            float a = 0.f, b2 = 0.f;
            #pragma unroll
            for (int i = 0; i < 8; i++) { a += ws1[i]; b2 += ws2[i]; }
            float mu = a / CS;
            float var = b2 / CS - mu*mu;
            mu_s = mu;
            rstd_s = rsqrtf(var + EPSV);
        }
        __syncthreads();
        float v = (val - mu_s) * rstd_s * lns_w[t] + lns_b[t];
        g_snh[((size_t)b*C + t)*SN + n] = __float2bfloat16(v);
    } else {
        // ----- wconv: weights -> bf16 -----
        int i = (bid - 1536) * 256 + tid;   // over C*C/2 pairs
        float2 a = ((const float2*)Wq)[i];
        ((unsigned*)g_wqh)[i] = pack_bf16(a.x, a.y);
        float2 b = ((const float2*)Wo)[i];
        ((unsigned*)g_woh)[i] = pack_bf16(b.x, b.y);
        float2 c = ((const float2*)Wk)[i];
        ((unsigned*)g_wkvh)[i] = pack_bf16(c.x, c.y);
        float2 d = ((const float2*)Wv)[i];
        ((unsigned*)g_wkvh)[i + C*C/2] = pack_bf16(d.x, d.y);
    }
}

// ---------------------------------------------------------------------------
// Shared GEMM mainloop (2-stage, BK=32), CTA tile 128x128, 8 warps 2(m)x4(n),
// warp tile 64x32. B fragments via ldmatrix.x4.trans (2 per k-half).
// acc[b,o,n] += sum_c W[o,c] * In[b,c,n] over c=0..255.
// ---------------------------------------------------------------------------
__device__ __forceinline__ void gemm_mainloop(
    const __nv_bfloat16* __restrict__ Wh,
    const __nv_bfloat16* __restrict__ Inb,
    int nb, int om, int nsize, int tid,
    float (&acc)[4][4][4],
    __nv_bfloat16 (&As)[2][128][40],
    __nv_bfloat16 (&Bs)[2][32][136])
{
    int w = tid >> 5, lane = tid & 31;
    int wr = w >> 2, wc = w & 3;

    int arow = tid >> 1, acol = (tid & 1) * 16;
    int brow = tid >> 3, bseg = (tid & 7) * 16;

    // ldmatrix.x4.trans addressing for B: lane L -> matrix m=L>>3, row r=L&7.
    // Matrix m covers k rows (m&1)*8.. and n cols (m>>1)*8.. relative to base.
    int bm = lane >> 3, brr = lane & 7;
    int b_krow = (bm & 1) * 8 + brr;
    int b_ncol = (bm >> 1) * 8;

    auto stage = [&](int buf, int k0) {
        const __nv_bfloat16* ap = Wh + (size_t)(om + arow)*C + k0 + acol;
        cp16(sptr(&As[buf][arow][acol]),     ap);
        cp16(sptr(&As[buf][arow][acol + 8]), ap + 8);
        const __nv_bfloat16* bp = Inb + (size_t)(k0 + brow)*nsize + nb + bseg;
        cp16(sptr(&Bs[buf][brow][bseg]),     bp);
        cp16(sptr(&Bs[buf][brow][bseg + 8]), bp + 8);
        cp_commit();
    };

    #pragma unroll
    for (int mi = 0; mi < 4; mi++)
        #pragma unroll
        for (int nj = 0; nj < 4; nj++)
            #pragma unroll
            for (int q = 0; q < 4; q++) acc[mi][nj][q] = 0.f;

    stage(0, 0);

    #pragma unroll 1
    for (int ks = 0; ks < 8; ks++) {
        int buf = ks & 1;
        cp_wait<0>();
        __syncthreads();

        // k half 0 (cols 0..15)
        unsigned afr[4][4], bq[2][4];
        #pragma unroll
        for (int mi = 0; mi < 4; mi++)
            ldsm_x4(afr[mi], sptr(&As[buf][64*wr + 16*mi + (lane & 15)][(lane >> 4) * 8]));
        // bq[h] covers n cols 32*wc + 16*h .. +16 (nj = 2h, 2h+1)
        ldsm_x4_trans(bq[0], sptr(&Bs[buf][b_krow][32*wc + b_ncol]));
        ldsm_x4_trans(bq[1], sptr(&Bs[buf][b_krow][32*wc + 16 + b_ncol]));

        if (ks < 7) stage(buf ^ 1, (ks + 1) * 32);

        #pragma unroll
        for (int nj = 0; nj < 4; nj++)
            #pragma unroll
            for (int mi = 0; mi < 4; mi++)
                mma16816(acc[mi][nj], afr[mi], &bq[nj >> 1][(nj & 1) * 2]);

        // k half 1 (cols 16..31)
        #pragma unroll
        for (int mi = 0; mi < 4; mi++)
            ldsm_x4(afr[mi], sptr(&As[buf][64*wr + 16*mi + (lane & 15)][16 + (lane >> 4) * 8]));
        ldsm_x4_trans(bq[0], sptr(&Bs[buf][16 + b_krow][32*wc + b_ncol]));
        ldsm_x4_trans(bq[1], sptr(&Bs[buf][16 + b_krow][32*wc + 16 + b_ncol]));
        #pragma unroll
        for (int nj = 0; nj < 4; nj++)
            #pragma unroll
            for (int mi = 0; mi < 4; mi++)
                mma16816(acc[mi][nj], afr[mi], &bq[nj >> 1][(nj & 1) * 2]);
    }
}

// ---------------------------------------------------------------------------
// Kernel 2: fused Q-GEMM + KV-GEMM. grid (128, 3, BB):
// y<2 -> Q (bf16 out); y==2 -> KV (x<8), K rows -> bf16, V rows -> fp16.
// ---------------------------------------------------------------------------
__global__ void __launch_bounds__(256) qkv_gemm() {
    __shared__ __nv_bfloat16 As[2][128][40];
    __shared__ __nv_bfloat16 Bs[2][32][136];

    int tid = threadIdx.x, w = tid >> 5, lane = tid & 31;
    int wr = w >> 2, wc = w & 3;
    int g = lane >> 2, tig = lane & 3;
    int b = blockIdx.z;
    float acc[4][4][4];

    if (blockIdx.y < 2) {
        int nb = blockIdx.x * 128, om = blockIdx.y * 128;
        gemm_mainloop(g_wqh, g_hnh + (size_t)b*C*NN, nb, om, NN, tid, acc, As, Bs);
        #pragma unroll
        for (int mi = 0; mi < 4; mi++) {
            int o = om + 64*wr + 16*mi + g;
            #pragma unroll
            for (int nj = 0; nj < 4; nj++) {
                int n = nb + 32*wc + 8*nj + 2*tig;
                size_t base0 = ((size_t)b*C + o)*NN + n;
                size_t base1 = ((size_t)b*C + o + 8)*NN + n;
                *(unsigned*)(g_qh + base0) = pack_bf16(acc[mi][nj][0], acc[mi][nj][1]);
                *(unsigned*)(g_qh + base1) = pack_bf16(acc[mi][nj][2], acc[mi][nj][3]);
            }
        }
    } else {
        if (blockIdx.x >= 8) return;
        int nb = (blockIdx.x & 1) * 128, om = (blockIdx.x >> 1) * 128;
        gemm_mainloop(g_wkvh, g_snh + (size_t)b*C*SN, nb, om, SN, tid, acc, As, Bs);
        #pragma unroll
        for (int mi = 0; mi < 4; mi++) {
            int o = om + 64*wr + 16*mi + g;
            #pragma unroll
            for (int nj = 0; nj < 4; nj++) {
                int n = nb + 32*wc + 8*nj + 2*tig;
                int oo = o & 255;
                size_t base0 = ((size_t)b*C + oo)*SN + n;
                size_t base1 = ((size_t)b*C + oo + 8)*SN + n;
                if (o < 256) {   // K -> bf16
                    *(unsigned*)(g_kh + base0) = pack_bf16(acc[mi][nj][0], acc[mi][nj][1]);
                    *(unsigned*)(g_kh + base1) = pack_bf16(acc[mi][nj][2], acc[mi][nj][3]);
                } else {         // V -> fp16
                    *(unsigned*)(g_vh + base0) = pack_f16(acc[mi][nj][0], acc[mi][nj][1]);
                    *(unsigned*)(g_vh + base1) = pack_f16(acc[mi][nj][2], acc[mi][nj][3]);
                }
            }
        }
    }
}

// ---------------------------------------------------------------------------
// Kernel 4: O-GEMM, fp32 out + bias + residual. grid (NN/128, C/128, BB).
// ---------------------------------------------------------------------------
__global__ void __launch_bounds__(256) o_gemm(float* __restrict__ OutF,
                                              const float* __restrict__ bias,
                                              const float* __restrict__ resid) {
    __shared__ __nv_bfloat16 As[2][128][40];
    __shared__ __nv_bfloat16 Bs[2][32][136];

    int tid = threadIdx.x, w = tid >> 5, lane = tid & 31;
    int wr = w >> 2, wc = w & 3;
    int g = lane >> 2, tig = lane & 3;
    int b = blockIdx.z;
    int nb = blockIdx.x * 128, om = blockIdx.y * 128;
    float acc[4][4][4];

    gemm_mainloop(g_woh, g_aoh + (size_t)b*C*NN, nb, om, NN, tid, acc, As, Bs);

    #pragma unroll
    for (int mi = 0; mi < 4; mi++) {
        int o = om + 64*wr + 16*mi + g;
        #pragma unroll
        for (int nj = 0; nj < 4; nj++) {
            int n = nb + 32*wc + 8*nj + 2*tig;
            size_t base0 = ((size_t)b*C + o)*NN + n;
            size_t base1 = ((size_t)b*C + o + 8)*NN + n;
            float bo0 = bias[o], bo1 = bias[o+8];
            float2 x0 = *(const float2*)(resid + base0);
            float2 x1 = *(const float2*)(resid + base1);
            float2 r0, r1;
            r0.x = acc[mi][nj][0] + bo0 + x0.x;
            r0.y = acc[mi][nj][1] + bo0 + x0.y;
            r1.x = acc[mi][nj][2] + bo1 + x1.x;
            r1.y = acc[mi][nj][3] + bo1 + x1.y;
            *(float2*)(OutF + base0) = r0;
            *(float2*)(OutF + base1) = r1;
        }
    }
}

// ---------------------------------------------------------------------------
// Kernel 3: attention. S = QK^T in bf16 mma; softmax exp via ex2.approx.f16x2
// (outputs ARE the fp16 PV A-fragments); l via extra mma against constant
// all-ones fp16 B-fragment. grid (NN/128, HEADS, BB), 256 threads (8 warps).
// ---------------------------------------------------------------------------
__global__ void __launch_bounds__(256) attn_kernel() {
    __shared__ __nv_bfloat16 qsh[128][34];   // Q [pos][d]; reused as O staging
    __shared__ __nv_bfloat16 ksh[SN][40];    // K [s][d]
    __shared__ __half        vsh[DH][264];   // V [d][s]  fp16

    int b = blockIdx.z, h = blockIdx.y;
    int nb = blockIdx.x * 128;
    int tid = threadIdx.x, w = tid >> 5, lane = tid & 31;
    int g = lane >> 2, tig = lane & 3;

    const __nv_bfloat16* kb = g_kh + ((size_t)b*C + h*DH)*SN;
    const __half*        vb = g_vh + ((size_t)b*C + h*DH)*SN;
    const __nv_bfloat16* qb = g_qh + ((size_t)b*C + h*DH)*NN;

    #pragma unroll
    for (int i = tid; i < DH*SN/8; i += 256) {
        int d = i & 31, cs = i >> 5;
        __nv_bfloat16 tmp[8];
        *(uint4*)tmp = *(const uint4*)(kb + (size_t)d*SN + cs*8);
        #pragma unroll
        for (int j = 0; j < 8; j++) ksh[cs*8 + j][d] = tmp[j];
    }
    #pragma unroll
    for (int i = tid; i < DH*SN/8; i += 256) {
        int d = i >> 5, cs = i & 31;
        *(uint4*)&vsh[d][cs*8] = *(const uint4*)(vb + (size_t)d*SN + cs*8);
    }
    {
        // fold softmax scale AND log2(e) into Q (softmax runs in exp2 domain)
        const float scf = 0.17677669529663689f * 1.4426950408889634f;
        const __nv_bfloat162 sc2 = __floats2bfloat162_rn(scf, scf);
        #pragma unroll
        for (int i = tid; i < 128*DH/8; i += 256) {
            int d = i >> 4, pc = i & 15;
            __nv_bfloat162 tmp[4];
            *(uint4*)tmp = *(const uint4*)(qb + (size_t)d*NN + nb + pc*8);
            #pragma unroll
            for (int j = 0; j < 4; j++) {
                __nv_bfloat162 v = __hmul2(tmp[j], sc2);
                qsh[pc*8 + 2*j    ][d] = __low2bfloat16(v);
                qsh[pc*8 + 2*j + 1][d] = __high2bfloat16(v);
            }
        }
    }
    __syncthreads();

    unsigned aq[2][4];
    {
        int m0 = 16*w;
        #pragma unroll
        for (int kg = 0; kg < 2; kg++) {
            int kc = 16*kg + 2*tig;
            aq[kg][0] = *(const unsigned*)&qsh[m0+g  ][kc];
            aq[kg][1] = *(const unsigned*)&qsh[m0+g+8][kc];
            aq[kg][2] = *(const unsigned*)&qsh[m0+g  ][kc+8];
            aq[kg][3] = *(const unsigned*)&qsh[m0+g+8][kc+8];
        }
    }

    float m0r = -INFINITY, m1r = -INFINITY;
    float oc[4][4];
    #pragma unroll
    for (int jj = 0; jj < 4; jj++)
        #pragma unroll
        for (int q = 0; q < 4; q++) oc[jj][q] = 0.f;
    float lacc[4] = {0.f, 0.f, 0.f, 0.f};   // l row-sums via ones-mma

    // precomputed ldmatrix address components
    int k_lrow = lane & 7, k_lcol = (lane >> 3) * 8;            // for ksh x4
    int v_mat = lane >> 3;
    int v_rlo = 8 * (v_mat >> 1) + (lane & 7);                  // row within 16-d group
    int v_col8 = 8 * (v_mat & 1);                               // s-half

    const unsigned bones[2] = {0x3C003C00u, 0x3C003C00u};       // fp16 1.0 x2

    for (int s0 = 0; s0 < SN; s0 += 64) {
        // --- S tile: 16 rows x 64 tokens; B-frags via ldmatrix.x4 ---
        float sc[8][4];
        #pragma unroll
        for (int j = 0; j < 8; j++) {
            sc[j][0] = sc[j][1] = sc[j][2] = sc[j][3] = 0.f;
            unsigned bk4[4];
            ldsm_x4(bk4, sptr(&ksh[s0 + 8*j + k_lrow][k_lcol]));
            mma16816(sc[j], aq[0], bk4);
            mma16816(sc[j], aq[1], bk4 + 2);
        }

        // --- online softmax: max, corr, f16x2 exp (results = A-fragments) ---
        float cm0 = -INFINITY, cm1 = -INFINITY;
        #pragma unroll
        for (int j = 0; j < 8; j++) {
            cm0 = fmaxf(cm0, fmaxf(sc[j][0], sc[j][1]));
            cm1 = fmaxf(cm1, fmaxf(sc[j][2], sc[j][3]));
        }
        cm0 = fmaxf(cm0, __shfl_xor_sync(0xffffffffu, cm0, 1));
        cm0 = fmaxf(cm0, __shfl_xor_sync(0xffffffffu, cm0, 2));
        cm1 = fmaxf(cm1, __shfl_xor_sync(0xffffffffu, cm1, 1));
        cm1 = fmaxf(cm1, __shfl_xor_sync(0xffffffffu, cm1, 2));

        float nm0 = fmaxf(m0r, cm0), nm1 = fmaxf(m1r, cm1);
        float corr0 = ex2f(m0r - nm0), corr1 = ex2f(m1r - nm1);
        m0r = nm0; m1r = nm1;

        unsigned ap[4][4];
        #pragma unroll
        for (int j = 0; j < 8; j++) {
            unsigned lo = ex2h2(sc[j][0] - nm0, sc[j][1] - nm0);
            unsigned hi = ex2h2(sc[j][2] - nm1, sc[j][3] - nm1);
            ap[j >> 1][(j & 1) * 2    ] = lo;
            ap[j >> 1][(j & 1) * 2 + 1] = hi;
        }

        #pragma unroll
        for (int jj = 0; jj < 4; jj++) {
            oc[jj][0] *= corr0; oc[jj][1] *= corr0;
            oc[jj][2] *= corr1; oc[jj][3] *= corr1;
        }
        lacc[0] *= corr0; lacc[1] *= corr0;
        lacc[2] *= corr1; lacc[3] *= corr1;

        // --- O += P V (f16 mma); l += P * ones ---
        #pragma unroll
        for (int kg = 0; kg < 4; kg++) {
            int scb = s0 + 16*kg + v_col8;
            #pragma unroll
            for (int p = 0; p < 2; p++) {
                unsigned bv4[4];
                ldsm_x4(bv4, sptr(&vsh[16*p + v_rlo][scb]));
                mma16816f16(oc[2*p],     ap[kg], bv4);
                mma16816f16(oc[2*p + 1], ap[kg], bv4 + 2);
            }
            mma16816f16(lacc, ap[kg], bones);
        }
    }

    float inv0 = 1.f / lacc[0], inv1 = 1.f / lacc[2];
    __syncthreads();
    #pragma unroll
    for (int jj = 0; jj < 4; jj++) {
        int col = 8*jj + 2*tig;
        *(unsigned*)&qsh[16*w+g  ][col] = pack_bf16(oc[jj][0]*inv0, oc[jj][1]*inv0);
        *(unsigned*)&qsh[16*w+g+8][col] = pack_bf16(oc[jj][2]*inv1, oc[jj][3]*inv1);
    }
    __syncthreads();
    #pragma unroll
    for (int i = tid; i < 128*DH/8; i += 256) {
        int d = i >> 4, pc = i & 15;
        __nv_bfloat16 tmp[8];
        #pragma unroll
        for (int j = 0; j < 8; j++) tmp[j] = qsh[pc*8 + j][d];
        *(uint4*)(g_aoh + ((size_t)b*C + h*DH + d)*NN + nb + pc*8) = *(uint4*)tmp;
    }
}

// ---------------------------------------------------------------------------
extern "C" void kernel_launch(void* const* d_in, const int* in_sizes, int n_in,
                              void* d_out, int out_size) {
    const float* x     = (const float*)d_in[0];
    const float* s     = (const float*)d_in[1];
    const float* ln_w  = (const float*)d_in[2];
    const float* ln_b  = (const float*)d_in[3];
    const float* lns_w = (const float*)d_in[4];
    const float* lns_b = (const float*)d_in[5];
    const float* Wq    = (const float*)d_in[6];
    const float* Wk    = (const float*)d_in[7];
    const float* Wv    = (const float*)d_in[8];
    const float* Wo    = (const float*)d_in[9];
    const float* bo    = (const float*)d_in[10];
    float* out = (float*)d_out;

    // 1: fused prep (wconv + lns + lnx)
    prep_kernel<<<1664, 256>>>(x, ln_w, ln_b, s, lns_w, lns_b, Wq, Wo, Wk, Wv);

    // 2: fused Q + KV GEMMs
    {
        dim3 grid(NN/128, 3, BB);
        qkv_gemm<<<grid, 256>>>();
    }

    // 3: attention
    {
        dim3 grid(NN/128, HEADS, BB);
        attn_kernel<<<grid, 256>>>();
    }

    // 4: out = Wo @ ao + bo + x
    {
        dim3 grid(NN/128, C/128, BB);
        o_gemm<<<grid, 256>>>(out, bo, x);
    }
}